// round 9
// baseline (speedup 1.0000x reference)
#include <cuda_runtime.h>
#include <cuda_bf16.h>
#include <cstdint>

#define N_NODES 100000
#define N_EDGES 1600000
#define D 128
#define N_CONVS 6

// ---------------- scratch (static device memory; no allocs allowed) ----------
__device__ __align__(16) float g_bufA[N_NODES * D];
__device__ __align__(16) float g_bufB[N_NODES * D];
// pre-split bf16 W, fragment-major: [layer][mat][kc(4)][hi:1024 | lo:1024] uint2
__device__ __align__(16) uint2 g_Wbf[N_CONVS * 2 * 4 * 2048];
__device__ float g_deg_inv[N_NODES];
__device__ int   g_deg[N_NODES];
__device__ int   g_row_ptr[N_NODES + 1];
__device__ int   g_cursor[N_NODES];
__device__ int   g_col_idx[N_EDGES];
__device__ int   g_blocksum[128];
__device__ int   g_is64;

// ---------------- helpers -----------------------------------------------------
__device__ __forceinline__ uint32_t packbf(float a, float b) {
    __nv_bfloat162 t = __floats2bfloat162_rn(a, b);   // .x = a (low half)
    return *(uint32_t*)&t;
}
__device__ __forceinline__ float bfhi(float w) {
    return __bfloat162float(__float2bfloat16_rn(w));
}

// ---------------- edge dtype detection ---------------------------------------
__global__ void detect_kernel(const void* __restrict__ ei) {
    const long long* p64 = (const long long*)ei;
    int ok = 1;
    for (int i = 0; i < 64; i++) {
        long long v = p64[i];
        if (v < 0 || v >= N_NODES) { ok = 0; break; }
    }
    g_is64 = ok;
}

__device__ __forceinline__ int load_edge(const void* ei, long idx) {
    long long v = g_is64 ? ((const long long*)ei)[idx]
                         : (long long)((const int*)ei)[idx];
    if ((unsigned long long)v >= (unsigned long long)N_NODES) v = 0;
    return (int)v;
}

// ---------------- CSR build --------------------------------------------------
__global__ void zero_deg_kernel() {
    int i = blockIdx.x * blockDim.x + threadIdx.x;
    if (i < N_NODES) g_deg[i] = 0;
}

__global__ void count_deg_kernel(const void* __restrict__ ei) {
    int e = blockIdx.x * blockDim.x + threadIdx.x;
    if (e < N_EDGES) atomicAdd(&g_deg[load_edge(ei, (long)N_EDGES + e)], 1);
}

#define SCAN_T 1024
#define SCAN_BLOCKS ((N_NODES + SCAN_T - 1) / SCAN_T)

__global__ __launch_bounds__(SCAN_T) void scanA_kernel() {
    __shared__ int sh[SCAN_T];
    int i = blockIdx.x * SCAN_T + threadIdx.x;
    int v = (i < N_NODES) ? g_deg[i] : 0;
    sh[threadIdx.x] = v;
    __syncthreads();
    int acc = v;
    for (int off = 1; off < SCAN_T; off <<= 1) {
        int t = (threadIdx.x >= off) ? sh[threadIdx.x - off] : 0;
        __syncthreads();
        acc += t;
        sh[threadIdx.x] = acc;
        __syncthreads();
    }
    if (i < N_NODES) g_row_ptr[i] = acc - v;
    if (threadIdx.x == SCAN_T - 1) g_blocksum[blockIdx.x] = acc;
}

__global__ void scanB_kernel() {
    __shared__ int sh[128];
    int t = threadIdx.x;
    int v = (t < SCAN_BLOCKS) ? g_blocksum[t] : 0;
    sh[t] = v;
    __syncthreads();
    int acc = v;
    for (int off = 1; off < 128; off <<= 1) {
        int tv = (t >= off) ? sh[t - off] : 0;
        __syncthreads();
        acc += tv;
        sh[t] = acc;
        __syncthreads();
    }
    if (t < SCAN_BLOCKS) g_blocksum[t] = acc - v;
}

__global__ __launch_bounds__(SCAN_T) void scanC_kernel() {
    int i = blockIdx.x * SCAN_T + threadIdx.x;
    if (i < N_NODES) {
        int r = g_row_ptr[i] + g_blocksum[blockIdx.x];
        g_row_ptr[i] = r;
        g_cursor[i] = r;
        g_deg_inv[i] = 1.0f / (float)max(g_deg[i], 1);
    }
    if (i == 0) g_row_ptr[N_NODES] = N_EDGES;
}

__global__ void fill_csr_kernel(const void* __restrict__ ei) {
    int e = blockIdx.x * blockDim.x + threadIdx.x;
    if (e < N_EDGES) {
        int src = load_edge(ei, e);
        int dst = load_edge(ei, (long)N_EDGES + e);
        int p = atomicAdd(&g_cursor[dst], 1);
        if (p < N_EDGES) g_col_idx[p] = src;
    }
}

// ---------------- W pre-split to bf16 fragment-major (once per launch) --------
__global__ void wsplit_kernel(const float* __restrict__ Wl,
                              const float* __restrict__ Wr) {
    int t = blockIdx.x * 256 + threadIdx.x;           // 6*2*4*1024
    if (t >= N_CONVS * 2 * 4 * 1024) return;
    int f     = t & 1023;
    int kc    = (t >> 10) & 3;
    int mat   = (t >> 12) & 1;
    int layer = t >> 13;
    int s  = f >> 9;
    int n  = (f >> 2) & 127;
    int qq = f & 3;
    const float* W = (mat ? Wr : Wl) + (long)layer * D * D;
    int kb = kc * 32 + s * 16 + 2 * qq;
    float w0 = W[(kb + 0) * D + n];
    float w1 = W[(kb + 1) * D + n];
    float w2 = W[(kb + 8) * D + n];
    float w3 = W[(kb + 9) * D + n];
    float h0 = bfhi(w0), h1 = bfhi(w1), h2 = bfhi(w2), h3 = bfhi(w3);
    uint2 hi, lo;
    hi.x = packbf(h0, h1);        hi.y = packbf(h2, h3);
    lo.x = packbf(w0 - h0, w1 - h1);
    lo.y = packbf(w2 - h2, w3 - h3);
    uint2* dst = g_Wbf + (long)(((layer * 2 + mat) * 4 + kc)) * 2048;
    dst[f] = hi;
    dst[1024 + f] = lo;
}

// ---------------- fused agg + 3xBF16 dual GEMM + bias + relu ------------------
// Block = 128 output rows. Phase A: warp-per-node gather-mean into smem.
// Phase B: dual GEMM (mean from smem, x from gmem) with hi/lo bf16 split.
#define APITCH 20
#define MPITCH 132
#define SM_MEAN  0
#define SM_AS    (128 * MPITCH)
#define SM_WS    (SM_AS + 2 * 128 * APITCH)
#define SMEM_FLOATS (SM_WS + 2 * 1024 * 2)
#define SMEM_BYTES (SMEM_FLOATS * 4)

__device__ __forceinline__ void mma_bf16(float c[4],
                                         uint32_t a0, uint32_t a1,
                                         uint32_t a2, uint32_t a3,
                                         uint32_t b0, uint32_t b1) {
    asm volatile(
        "mma.sync.aligned.m16n8k16.row.col.f32.bf16.bf16.f32 "
        "{%0,%1,%2,%3}, {%4,%5,%6,%7}, {%8,%9}, {%0,%1,%2,%3};"
        : "+f"(c[0]), "+f"(c[1]), "+f"(c[2]), "+f"(c[3])
        : "r"(a0), "r"(a1), "r"(a2), "r"(a3), "r"(b0), "r"(b1));
}

__global__ __launch_bounds__(256, 2) void sage_fused(
    const float* __restrict__ X,     // input features [N,128]
    const uint2* __restrict__ Wbf,   // this layer: 8*2048 uint2
    const float* __restrict__ bias,  // [128]
    float* __restrict__ Y)
{
    extern __shared__ __align__(16) float sm[];
    float*    mean_s = sm + SM_MEAN;
    uint32_t* As     = (uint32_t*)(sm + SM_AS);      // [2][128][APITCH]
    uint2*    Ws     = (uint2*)(sm + SM_WS);         // [2][1024]

    const int tid  = threadIdx.x;
    const int wid  = tid >> 5;
    const int lane = tid & 31;
    const int rr   = lane >> 2;
    const int qq   = lane & 3;
    const int wm   = (wid & 3) * 32;
    const int wn   = (wid >> 2) * 64;
    const int row0 = blockIdx.x * 128;

    // ---------- Phase A: gather-mean 128 nodes (warp per node, 16 each) ------
    const float4* x4 = (const float4*)X;
    for (int i = 0; i < 16; i++) {
        int loc = wid * 16 + i;
        int node = row0 + loc;
        float4 a0 = make_float4(0.f, 0.f, 0.f, 0.f);
        float4 a1 = a0, a2 = a0, a3 = a0;
        if (node < N_NODES) {
            int e0 = g_row_ptr[node];
            int e1 = g_row_ptr[node + 1];
            int e = e0;
            for (; e + 4 <= e1; e += 4) {
                int s0 = g_col_idx[e + 0];
                int s1 = g_col_idx[e + 1];
                int s2 = g_col_idx[e + 2];
                int s3 = g_col_idx[e + 3];
                float4 v0 = __ldg(&x4[(long)s0 * 32 + lane]);
                float4 v1 = __ldg(&x4[(long)s1 * 32 + lane]);
                float4 v2 = __ldg(&x4[(long)s2 * 32 + lane]);
                float4 v3 = __ldg(&x4[(long)s3 * 32 + lane]);
                a0.x += v0.x; a0.y += v0.y; a0.z += v0.z; a0.w += v0.w;
                a1.x += v1.x; a1.y += v1.y; a1.z += v1.z; a1.w += v1.w;
                a2.x += v2.x; a2.y += v2.y; a2.z += v2.z; a2.w += v2.w;
                a3.x += v3.x; a3.y += v3.y; a3.z += v3.z; a3.w += v3.w;
            }
            for (; e < e1; e++) {
                int s = g_col_idx[e];
                float4 v = __ldg(&x4[(long)s * 32 + lane]);
                a0.x += v.x; a0.y += v.y; a0.z += v.z; a0.w += v.w;
            }
            float di = g_deg_inv[node];
            a0.x = (a0.x + a1.x + a2.x + a3.x) * di;
            a0.y = (a0.y + a1.y + a2.y + a3.y) * di;
            a0.z = (a0.z + a1.z + a2.z + a3.z) * di;
            a0.w = (a0.w + a1.w + a2.w + a3.w) * di;
        }
        *(float4*)&mean_s[loc * MPITCH + lane * 4] = a0;
    }
    __syncthreads();

    // ---------- Phase B: dual GEMM ------------------------------------------
    float c[2][8][4];
#pragma unroll
    for (int mt = 0; mt < 2; mt++)
#pragma unroll
        for (int nt = 0; nt < 8; nt++)
#pragma unroll
            for (int i = 0; i < 4; i++) c[mt][nt][i] = 0.f;

    for (int phase = 0; phase < 2; ++phase) {
        for (int kc = 0; kc < 4; kc++) {
            // --- A tile: 128 rows x 32 k, split to bf16 hi/lo packed pairs ---
#pragma unroll
            for (int i = 0; i < 4; i++) {
                int idx = tid + i * 256;            // 0..1023 float4 slots
                int r  = idx >> 3;
                int c4 = idx & 7;
                float4 v;
                if (phase == 0) {
                    v = *(float4*)&mean_s[r * MPITCH + (kc * 8 + c4) * 4];
                } else {
                    int rg = row0 + r;
                    if (rg >= N_NODES) rg = N_NODES - 1;
                    v = x4[(long)rg * 32 + kc * 8 + c4];
                }
                float hx = bfhi(v.x), hy = bfhi(v.y), hz = bfhi(v.z), hw = bfhi(v.w);
                As[r * APITCH + c4 * 2 + 0] = packbf(hx, hy);
                As[r * APITCH + c4 * 2 + 1] = packbf(hz, hw);
                As[128 * APITCH + r * APITCH + c4 * 2 + 0] = packbf(v.x - hx, v.y - hy);
                As[128 * APITCH + r * APITCH + c4 * 2 + 1] = packbf(v.z - hz, v.w - hw);
            }
            // --- W tile: linear 16KB copy (hi 8KB | lo 8KB) ---
            {
                const uint4* src = (const uint4*)(Wbf + (long)(phase * 4 + kc) * 2048);
                uint4* dst = (uint4*)Ws;
#pragma unroll
                for (int i = 0; i < 4; i++) {
                    int idx = tid + i * 256;        // 0..1023 uint4
                    dst[idx] = src[idx];
                }
            }
            __syncthreads();

#pragma unroll
            for (int s = 0; s < 2; s++) {
                uint32_t ah[2][4], al[2][4];
#pragma unroll
                for (int mt = 0; mt < 2; mt++) {
                    int r = wm + mt * 16 + rr;
                    int p = s * 8 + qq;
                    ah[mt][0] = As[r * APITCH + p];
                    ah[mt][1] = As[(r + 8) * APITCH + p];
                    ah[mt][2] = As[r * APITCH + p + 4];
                    ah[mt][3] = As[(r + 8) * APITCH + p + 4];
                    al[mt][0] = As[128 * APITCH + r * APITCH + p];
                    al[mt][1] = As[128 * APITCH + (r + 8) * APITCH + p];
                    al[mt][2] = As[128 * APITCH + r * APITCH + p + 4];
                    al[mt][3] = As[128 * APITCH + (r + 8) * APITCH + p + 4];
                }
#pragma unroll
                for (int nt = 0; nt < 8; nt++) {
                    int widx = (s * 128 + wn + nt * 8 + rr) * 4 + qq;
                    uint2 bh = Ws[widx];
                    uint2 bl = Ws[1024 + widx];
#pragma unroll
                    for (int mt = 0; mt < 2; mt++) {
                        mma_bf16(c[mt][nt], ah[mt][0], ah[mt][1], ah[mt][2], ah[mt][3], bh.x, bh.y);
                        mma_bf16(c[mt][nt], ah[mt][0], ah[mt][1], ah[mt][2], ah[mt][3], bl.x, bl.y);
                        mma_bf16(c[mt][nt], al[mt][0], al[mt][1], al[mt][2], al[mt][3], bh.x, bh.y);
                    }
                }
            }
            __syncthreads();
        }
    }

    // epilogue: bias + relu
#pragma unroll
    for (int mt = 0; mt < 2; mt++) {
#pragma unroll
        for (int half = 0; half < 2; half++) {
            int r = row0 + wm + mt * 16 + rr + half * 8;
            if (r < N_NODES) {
#pragma unroll
                for (int nt = 0; nt < 8; nt++) {
                    int col = wn + nt * 8 + 2 * qq;
                    float v0 = c[mt][nt][half * 2 + 0] + bias[col];
                    float v1 = c[mt][nt][half * 2 + 1] + bias[col + 1];
                    float2 o;
                    o.x = fmaxf(v0, 0.f);
                    o.y = fmaxf(v1, 0.f);
                    *(float2*)&Y[(long)r * 128 + col] = o;
                }
            }
        }
    }
}

// ---------------- final linear ------------------------------------------------
__global__ __launch_bounds__(256) void final_kernel(
    const float* __restrict__ x, const float* __restrict__ W_lin,
    const float* __restrict__ b_lin, float* __restrict__ out)
{
    int warp = (blockIdx.x * blockDim.x + threadIdx.x) >> 5;
    int lane = threadIdx.x & 31;
    if (warp >= N_NODES) return;

    const float4* x4 = (const float4*)x;
    float4 xv = x4[(long)warp * 32 + lane];
    float w0 = W_lin[lane * 4 + 0];
    float w1 = W_lin[lane * 4 + 1];
    float w2 = W_lin[lane * 4 + 2];
    float w3 = W_lin[lane * 4 + 3];
    float s = xv.x * w0 + xv.y * w1 + xv.z * w2 + xv.w * w3;
#pragma unroll
    for (int off = 16; off > 0; off >>= 1)
        s += __shfl_xor_sync(0xFFFFFFFFu, s, off);
    if (lane == 0) out[warp] = s + b_lin[0];
}

// ---------------- launch ------------------------------------------------------
extern "C" void kernel_launch(void* const* d_in, const int* in_sizes, int n_in,
                              void* d_out, int out_size)
{
    const float* x     = (const float*)d_in[0];
    const void*  ei    = d_in[1];
    const float* Wl    = (const float*)d_in[2];
    const float* Wr    = (const float*)d_in[3];
    const float* b     = (const float*)d_in[4];
    const float* W_lin = (const float*)d_in[5];
    const float* b_lin = (const float*)d_in[6];
    float*       out   = (float*)d_out;

    float *bufA, *bufB;
    uint2* wbf;
    cudaGetSymbolAddress((void**)&bufA, g_bufA);
    cudaGetSymbolAddress((void**)&bufB, g_bufB);
    cudaGetSymbolAddress((void**)&wbf, g_Wbf);

    cudaFuncSetAttribute(sage_fused,
                         cudaFuncAttributeMaxDynamicSharedMemorySize, SMEM_BYTES);

    detect_kernel<<<1, 1>>>(ei);
    zero_deg_kernel<<<(N_NODES + 255) / 256, 256>>>();
    count_deg_kernel<<<(N_EDGES + 255) / 256, 256>>>(ei);
    scanA_kernel<<<SCAN_BLOCKS, SCAN_T>>>();
    scanB_kernel<<<1, 128>>>();
    scanC_kernel<<<SCAN_BLOCKS, SCAN_T>>>();
    fill_csr_kernel<<<(N_EDGES + 255) / 256, 256>>>(ei);
    wsplit_kernel<<<(N_CONVS * 2 * 4 * 1024 + 255) / 256, 256>>>(Wl, Wr);

    const int gemmBlocks = (N_NODES + 127) / 128;

    const float* cur = x;
    for (int i = 0; i < N_CONVS; i++) {
        float* nxt = (i & 1) ? bufB : bufA;
        sage_fused<<<gemmBlocks, 256, SMEM_BYTES>>>(
            cur, wbf + (long)i * 8 * 2048, b + (long)i * D, nxt);
        cur = nxt;
    }
    final_kernel<<<(N_NODES * 32 + 255) / 256, 256>>>(cur, W_lin, b_lin, out);
}

// round 10
// speedup vs baseline: 1.1198x; 1.1198x over previous
#include <cuda_runtime.h>
#include <cuda_bf16.h>
#include <cstdint>

#define N_NODES 100000
#define N_EDGES 1600000
#define D 128
#define N_CONVS 6

// ---------------- scratch (static device memory; no allocs allowed) ----------
__device__ __align__(16) float g_bufA[N_NODES * D];
__device__ __align__(16) float g_bufB[N_NODES * D];
// pre-split bf16 W, fragment-major: [layer][mat][kc(4)][hi:1024 | lo:1024] uint2
__device__ __align__(16) uint2 g_Wbf[N_CONVS * 2 * 4 * 2048];
__device__ float g_deg_inv[N_NODES];
__device__ int   g_deg[N_NODES];
__device__ int   g_row_ptr[N_NODES + 1];
__device__ int   g_cursor[N_NODES];
__device__ int   g_col_idx[N_EDGES];
__device__ int   g_blocksum[128];
__device__ int   g_is64;

// ---------------- helpers -----------------------------------------------------
__device__ __forceinline__ uint32_t packbf(float a, float b) {
    __nv_bfloat162 t = __floats2bfloat162_rn(a, b);   // .x = a (low half)
    return *(uint32_t*)&t;
}
__device__ __forceinline__ float bfhi(float w) {
    return __bfloat162float(__float2bfloat16_rn(w));
}

// ---------------- edge dtype detection ---------------------------------------
__global__ void detect_kernel(const void* __restrict__ ei) {
    const long long* p64 = (const long long*)ei;
    int ok = 1;
    for (int i = 0; i < 64; i++) {
        long long v = p64[i];
        if (v < 0 || v >= N_NODES) { ok = 0; break; }
    }
    g_is64 = ok;
}

__device__ __forceinline__ int load_edge(const void* ei, long idx) {
    long long v = g_is64 ? ((const long long*)ei)[idx]
                         : (long long)((const int*)ei)[idx];
    if ((unsigned long long)v >= (unsigned long long)N_NODES) v = 0;
    return (int)v;
}

// ---------------- CSR build --------------------------------------------------
__global__ void zero_deg_kernel() {
    int i = blockIdx.x * blockDim.x + threadIdx.x;
    if (i < N_NODES) g_deg[i] = 0;
}

__global__ void count_deg_kernel(const void* __restrict__ ei) {
    int e = blockIdx.x * blockDim.x + threadIdx.x;
    if (e < N_EDGES) atomicAdd(&g_deg[load_edge(ei, (long)N_EDGES + e)], 1);
}

#define SCAN_T 1024
#define SCAN_BLOCKS ((N_NODES + SCAN_T - 1) / SCAN_T)

__global__ __launch_bounds__(SCAN_T) void scanA_kernel() {
    __shared__ int sh[SCAN_T];
    int i = blockIdx.x * SCAN_T + threadIdx.x;
    int v = (i < N_NODES) ? g_deg[i] : 0;
    sh[threadIdx.x] = v;
    __syncthreads();
    int acc = v;
    for (int off = 1; off < SCAN_T; off <<= 1) {
        int t = (threadIdx.x >= off) ? sh[threadIdx.x - off] : 0;
        __syncthreads();
        acc += t;
        sh[threadIdx.x] = acc;
        __syncthreads();
    }
    if (i < N_NODES) g_row_ptr[i] = acc - v;
    if (threadIdx.x == SCAN_T - 1) g_blocksum[blockIdx.x] = acc;
}

__global__ void scanB_kernel() {
    __shared__ int sh[128];
    int t = threadIdx.x;
    int v = (t < SCAN_BLOCKS) ? g_blocksum[t] : 0;
    sh[t] = v;
    __syncthreads();
    int acc = v;
    for (int off = 1; off < 128; off <<= 1) {
        int tv = (t >= off) ? sh[t - off] : 0;
        __syncthreads();
        acc += tv;
        sh[t] = acc;
        __syncthreads();
    }
    if (t < SCAN_BLOCKS) g_blocksum[t] = acc - v;
}

__global__ __launch_bounds__(SCAN_T) void scanC_kernel() {
    int i = blockIdx.x * SCAN_T + threadIdx.x;
    if (i < N_NODES) {
        int r = g_row_ptr[i] + g_blocksum[blockIdx.x];
        g_row_ptr[i] = r;
        g_cursor[i] = r;
        g_deg_inv[i] = 1.0f / (float)max(g_deg[i], 1);
    }
    if (i == 0) g_row_ptr[N_NODES] = N_EDGES;
}

__global__ void fill_csr_kernel(const void* __restrict__ ei) {
    int e = blockIdx.x * blockDim.x + threadIdx.x;
    if (e < N_EDGES) {
        int src = load_edge(ei, e);
        int dst = load_edge(ei, (long)N_EDGES + e);
        int p = atomicAdd(&g_cursor[dst], 1);
        if (p < N_EDGES) g_col_idx[p] = src;
    }
}

// ---------------- W pre-split to bf16 fragment-major (once per launch) --------
__global__ void wsplit_kernel(const float* __restrict__ Wl,
                              const float* __restrict__ Wr) {
    int t = blockIdx.x * 256 + threadIdx.x;           // 6*2*4*1024
    if (t >= N_CONVS * 2 * 4 * 1024) return;
    int f     = t & 1023;
    int kc    = (t >> 10) & 3;
    int mat   = (t >> 12) & 1;
    int layer = t >> 13;
    int s  = f >> 9;
    int n  = (f >> 2) & 127;
    int qq = f & 3;
    const float* W = (mat ? Wr : Wl) + (long)layer * D * D;
    int kb = kc * 32 + s * 16 + 2 * qq;
    float w0 = W[(kb + 0) * D + n];
    float w1 = W[(kb + 1) * D + n];
    float w2 = W[(kb + 8) * D + n];
    float w3 = W[(kb + 9) * D + n];
    float h0 = bfhi(w0), h1 = bfhi(w1), h2 = bfhi(w2), h3 = bfhi(w3);
    uint2 hi, lo;
    hi.x = packbf(h0, h1);        hi.y = packbf(h2, h3);
    lo.x = packbf(w0 - h0, w1 - h1);
    lo.y = packbf(w2 - h2, w3 - h3);
    uint2* dst = g_Wbf + (long)(((layer * 2 + mat) * 4 + kc)) * 2048;
    dst[f] = hi;
    dst[1024 + f] = lo;
}

// ---------------- fused agg + 3xBF16 dual GEMM + bias + relu ------------------
// Block = 128 output rows. Phase A: warp-per-node gather-mean into smem,
// 8-deep independent accumulators (keeps ~128 in-flight loads/SM at 2 CTAs).
// Phase B: dual GEMM (mean from smem, x from gmem) with hi/lo bf16 split.
#define APITCH 20
#define MPITCH 132
#define SM_MEAN  0
#define SM_AS    (128 * MPITCH)
#define SM_WS    (SM_AS + 2 * 128 * APITCH)
#define SMEM_FLOATS (SM_WS + 2 * 1024 * 2)
#define SMEM_BYTES (SMEM_FLOATS * 4)

__device__ __forceinline__ void mma_bf16(float c[4],
                                         uint32_t a0, uint32_t a1,
                                         uint32_t a2, uint32_t a3,
                                         uint32_t b0, uint32_t b1) {
    asm volatile(
        "mma.sync.aligned.m16n8k16.row.col.f32.bf16.bf16.f32 "
        "{%0,%1,%2,%3}, {%4,%5,%6,%7}, {%8,%9}, {%0,%1,%2,%3};"
        : "+f"(c[0]), "+f"(c[1]), "+f"(c[2]), "+f"(c[3])
        : "r"(a0), "r"(a1), "r"(a2), "r"(a3), "r"(b0), "r"(b1));
}

#define FADD4(a, v) { (a).x += (v).x; (a).y += (v).y; (a).z += (v).z; (a).w += (v).w; }

__global__ __launch_bounds__(256, 2) void sage_fused(
    const float* __restrict__ X,     // input features [N,128]
    const uint2* __restrict__ Wbf,   // this layer: 8*2048 uint2
    const float* __restrict__ bias,  // [128]
    float* __restrict__ Y)
{
    extern __shared__ __align__(16) float sm[];
    float*    mean_s = sm + SM_MEAN;
    uint32_t* As     = (uint32_t*)(sm + SM_AS);      // [2][128][APITCH]
    uint2*    Ws     = (uint2*)(sm + SM_WS);         // [2][1024]

    const int tid  = threadIdx.x;
    const int wid  = tid >> 5;
    const int lane = tid & 31;
    const int rr   = lane >> 2;
    const int qq   = lane & 3;
    const int wm   = (wid & 3) * 32;
    const int wn   = (wid >> 2) * 64;
    const int row0 = blockIdx.x * 128;

    // ---------- Phase A: gather-mean, 8-deep ILP ------------------------------
    const float4* x4 = (const float4*)X;
    for (int i = 0; i < 16; i++) {
        int loc = wid * 16 + i;
        int node = row0 + loc;
        float4 a0 = make_float4(0.f, 0.f, 0.f, 0.f);
        float4 a1 = a0, a2 = a0, a3 = a0, a4 = a0, a5 = a0, a6 = a0, a7 = a0;
        if (node < N_NODES) {
            int e0 = g_row_ptr[node];
            int e1 = g_row_ptr[node + 1];
            int e = e0;
            for (; e + 8 <= e1; e += 8) {
                int s0 = g_col_idx[e + 0];
                int s1 = g_col_idx[e + 1];
                int s2 = g_col_idx[e + 2];
                int s3 = g_col_idx[e + 3];
                int s4 = g_col_idx[e + 4];
                int s5 = g_col_idx[e + 5];
                int s6 = g_col_idx[e + 6];
                int s7 = g_col_idx[e + 7];
                float4 v0 = __ldg(&x4[(long)s0 * 32 + lane]);
                float4 v1 = __ldg(&x4[(long)s1 * 32 + lane]);
                float4 v2 = __ldg(&x4[(long)s2 * 32 + lane]);
                float4 v3 = __ldg(&x4[(long)s3 * 32 + lane]);
                float4 v4 = __ldg(&x4[(long)s4 * 32 + lane]);
                float4 v5 = __ldg(&x4[(long)s5 * 32 + lane]);
                float4 v6 = __ldg(&x4[(long)s6 * 32 + lane]);
                float4 v7 = __ldg(&x4[(long)s7 * 32 + lane]);
                FADD4(a0, v0); FADD4(a1, v1); FADD4(a2, v2); FADD4(a3, v3);
                FADD4(a4, v4); FADD4(a5, v5); FADD4(a6, v6); FADD4(a7, v7);
            }
            for (; e + 2 <= e1; e += 2) {
                int s0 = g_col_idx[e + 0];
                int s1 = g_col_idx[e + 1];
                float4 v0 = __ldg(&x4[(long)s0 * 32 + lane]);
                float4 v1 = __ldg(&x4[(long)s1 * 32 + lane]);
                FADD4(a0, v0); FADD4(a1, v1);
            }
            if (e < e1) {
                int s = g_col_idx[e];
                float4 v = __ldg(&x4[(long)s * 32 + lane]);
                FADD4(a0, v);
            }
            float di = g_deg_inv[node];
            a0.x = (a0.x + a1.x + a2.x + a3.x + a4.x + a5.x + a6.x + a7.x) * di;
            a0.y = (a0.y + a1.y + a2.y + a3.y + a4.y + a5.y + a6.y + a7.y) * di;
            a0.z = (a0.z + a1.z + a2.z + a3.z + a4.z + a5.z + a6.z + a7.z) * di;
            a0.w = (a0.w + a1.w + a2.w + a3.w + a4.w + a5.w + a6.w + a7.w) * di;
        }
        *(float4*)&mean_s[loc * MPITCH + lane * 4] = a0;
    }
    __syncthreads();

    // ---------- Phase B: dual GEMM ------------------------------------------
    float c[2][8][4];
#pragma unroll
    for (int mt = 0; mt < 2; mt++)
#pragma unroll
        for (int nt = 0; nt < 8; nt++)
#pragma unroll
            for (int i = 0; i < 4; i++) c[mt][nt][i] = 0.f;

    for (int phase = 0; phase < 2; ++phase) {
        for (int kc = 0; kc < 4; kc++) {
            // --- A tile: 128 rows x 32 k, split to bf16 hi/lo packed pairs ---
#pragma unroll
            for (int i = 0; i < 4; i++) {
                int idx = tid + i * 256;            // 0..1023 float4 slots
                int r  = idx >> 3;
                int c4 = idx & 7;
                float4 v;
                if (phase == 0) {
                    v = *(float4*)&mean_s[r * MPITCH + (kc * 8 + c4) * 4];
                } else {
                    int rg = row0 + r;
                    if (rg >= N_NODES) rg = N_NODES - 1;
                    v = x4[(long)rg * 32 + kc * 8 + c4];
                }
                float hx = bfhi(v.x), hy = bfhi(v.y), hz = bfhi(v.z), hw = bfhi(v.w);
                As[r * APITCH + c4 * 2 + 0] = packbf(hx, hy);
                As[r * APITCH + c4 * 2 + 1] = packbf(hz, hw);
                As[128 * APITCH + r * APITCH + c4 * 2 + 0] = packbf(v.x - hx, v.y - hy);
                As[128 * APITCH + r * APITCH + c4 * 2 + 1] = packbf(v.z - hz, v.w - hw);
            }
            // --- W tile: linear 16KB copy (hi 8KB | lo 8KB) ---
            {
                const uint4* src = (const uint4*)(Wbf + (long)(phase * 4 + kc) * 2048);
                uint4* dst = (uint4*)Ws;
#pragma unroll
                for (int i = 0; i < 4; i++) {
                    int idx = tid + i * 256;        // 0..1023 uint4
                    dst[idx] = src[idx];
                }
            }
            __syncthreads();

#pragma unroll
            for (int s = 0; s < 2; s++) {
                uint32_t ah[2][4], al[2][4];
#pragma unroll
                for (int mt = 0; mt < 2; mt++) {
                    int r = wm + mt * 16 + rr;
                    int p = s * 8 + qq;
                    ah[mt][0] = As[r * APITCH + p];
                    ah[mt][1] = As[(r + 8) * APITCH + p];
                    ah[mt][2] = As[r * APITCH + p + 4];
                    ah[mt][3] = As[(r + 8) * APITCH + p + 4];
                    al[mt][0] = As[128 * APITCH + r * APITCH + p];
                    al[mt][1] = As[128 * APITCH + (r + 8) * APITCH + p];
                    al[mt][2] = As[128 * APITCH + r * APITCH + p + 4];
                    al[mt][3] = As[128 * APITCH + (r + 8) * APITCH + p + 4];
                }
#pragma unroll
                for (int nt = 0; nt < 8; nt++) {
                    int widx = (s * 128 + wn + nt * 8 + rr) * 4 + qq;
                    uint2 bh = Ws[widx];
                    uint2 bl = Ws[1024 + widx];
#pragma unroll
                    for (int mt = 0; mt < 2; mt++) {
                        mma_bf16(c[mt][nt], ah[mt][0], ah[mt][1], ah[mt][2], ah[mt][3], bh.x, bh.y);
                        mma_bf16(c[mt][nt], ah[mt][0], ah[mt][1], ah[mt][2], ah[mt][3], bl.x, bl.y);
                        mma_bf16(c[mt][nt], al[mt][0], al[mt][1], al[mt][2], al[mt][3], bh.x, bh.y);
                    }
                }
            }
            __syncthreads();
        }
    }

    // epilogue: bias + relu
#pragma unroll
    for (int mt = 0; mt < 2; mt++) {
#pragma unroll
        for (int half = 0; half < 2; half++) {
            int r = row0 + wm + mt * 16 + rr + half * 8;
            if (r < N_NODES) {
#pragma unroll
                for (int nt = 0; nt < 8; nt++) {
                    int col = wn + nt * 8 + 2 * qq;
                    float v0 = c[mt][nt][half * 2 + 0] + bias[col];
                    float v1 = c[mt][nt][half * 2 + 1] + bias[col + 1];
                    float2 o;
                    o.x = fmaxf(v0, 0.f);
                    o.y = fmaxf(v1, 0.f);
                    *(float2*)&Y[(long)r * 128 + col] = o;
                }
            }
        }
    }
}

// ---------------- final linear ------------------------------------------------
__global__ __launch_bounds__(256) void final_kernel(
    const float* __restrict__ x, const float* __restrict__ W_lin,
    const float* __restrict__ b_lin, float* __restrict__ out)
{
    int warp = (blockIdx.x * blockDim.x + threadIdx.x) >> 5;
    int lane = threadIdx.x & 31;
    if (warp >= N_NODES) return;

    const float4* x4 = (const float4*)x;
    float4 xv = x4[(long)warp * 32 + lane];
    float w0 = W_lin[lane * 4 + 0];
    float w1 = W_lin[lane * 4 + 1];
    float w2 = W_lin[lane * 4 + 2];
    float w3 = W_lin[lane * 4 + 3];
    float s = xv.x * w0 + xv.y * w1 + xv.z * w2 + xv.w * w3;
#pragma unroll
    for (int off = 16; off > 0; off >>= 1)
        s += __shfl_xor_sync(0xFFFFFFFFu, s, off);
    if (lane == 0) out[warp] = s + b_lin[0];
}

// ---------------- launch ------------------------------------------------------
extern "C" void kernel_launch(void* const* d_in, const int* in_sizes, int n_in,
                              void* d_out, int out_size)
{
    const float* x     = (const float*)d_in[0];
    const void*  ei    = d_in[1];
    const float* Wl    = (const float*)d_in[2];
    const float* Wr    = (const float*)d_in[3];
    const float* b     = (const float*)d_in[4];
    const float* W_lin = (const float*)d_in[5];
    const float* b_lin = (const float*)d_in[6];
    float*       out   = (float*)d_out;

    float *bufA, *bufB;
    uint2* wbf;
    cudaGetSymbolAddress((void**)&bufA, g_bufA);
    cudaGetSymbolAddress((void**)&bufB, g_bufB);
    cudaGetSymbolAddress((void**)&wbf, g_Wbf);

    cudaFuncSetAttribute(sage_fused,
                         cudaFuncAttributeMaxDynamicSharedMemorySize, SMEM_BYTES);

    detect_kernel<<<1, 1>>>(ei);
    zero_deg_kernel<<<(N_NODES + 255) / 256, 256>>>();
    count_deg_kernel<<<(N_EDGES + 255) / 256, 256>>>(ei);
    scanA_kernel<<<SCAN_BLOCKS, SCAN_T>>>();
    scanB_kernel<<<1, 128>>>();
    scanC_kernel<<<SCAN_BLOCKS, SCAN_T>>>();
    fill_csr_kernel<<<(N_EDGES + 255) / 256, 256>>>(ei);
    wsplit_kernel<<<(N_CONVS * 2 * 4 * 1024 + 255) / 256, 256>>>(Wl, Wr);

    const int gemmBlocks = (N_NODES + 127) / 128;

    const float* cur = x;
    for (int i = 0; i < N_CONVS; i++) {
        float* nxt = (i & 1) ? bufB : bufA;
        sage_fused<<<gemmBlocks, 256, SMEM_BYTES>>>(
            cur, wbf + (long)i * 8 * 2048, b + (long)i * D, nxt);
        cur = nxt;
    }
    final_kernel<<<(N_NODES * 32 + 255) / 256, 256>>>(cur, W_lin, b_lin, out);
}

// round 12
// speedup vs baseline: 1.5285x; 1.3650x over previous
#include <cuda_runtime.h>
#include <cuda_bf16.h>
#include <cstdint>

#define N_NODES 100000
#define N_EDGES 1600000
#define D 128
#define N_CONVS 6

// ---------------- scratch (static device memory; no allocs allowed) ----------
__device__ __align__(16) float g_bufA[N_NODES * D];
__device__ __align__(16) float g_bufB[N_NODES * D];
__device__ __align__(16) float g_mean[N_NODES * D];
// pre-split bf16 W, fragment-major: [layer][mat][kc(4)][hi:1024 | lo:1024] uint2
__device__ __align__(16) uint2 g_Wbf[N_CONVS * 2 * 4 * 2048];
__device__ float g_deg_inv[N_NODES];
__device__ int   g_deg[N_NODES];
__device__ int   g_row_ptr[N_NODES + 1];
__device__ int   g_cursor[N_NODES];
__device__ int   g_col_idx[N_EDGES];
__device__ int   g_blocksum[128];
__device__ int   g_is64;

// ---------------- helpers -----------------------------------------------------
__device__ __forceinline__ uint32_t packbf(float a, float b) {
    __nv_bfloat162 t = __floats2bfloat162_rn(a, b);   // .x = a (low half)
    return *(uint32_t*)&t;
}
__device__ __forceinline__ float bfhi(float w) {
    return __bfloat162float(__float2bfloat16_rn(w));
}

// ---------------- edge dtype detection ---------------------------------------
__global__ void detect_kernel(const void* __restrict__ ei) {
    const long long* p64 = (const long long*)ei;
    int ok = 1;
    for (int i = 0; i < 64; i++) {
        long long v = p64[i];
        if (v < 0 || v >= N_NODES) { ok = 0; break; }
    }
    g_is64 = ok;
}

__device__ __forceinline__ int load_edge(const void* ei, long idx) {
    long long v = g_is64 ? ((const long long*)ei)[idx]
                         : (long long)((const int*)ei)[idx];
    if ((unsigned long long)v >= (unsigned long long)N_NODES) v = 0;
    return (int)v;
}

// ---------------- CSR build --------------------------------------------------
__global__ void zero_deg_kernel() {
    int i = blockIdx.x * blockDim.x + threadIdx.x;
    if (i < N_NODES) g_deg[i] = 0;
}

__global__ void count_deg_kernel(const void* __restrict__ ei) {
    int e = blockIdx.x * blockDim.x + threadIdx.x;
    if (e < N_EDGES) atomicAdd(&g_deg[load_edge(ei, (long)N_EDGES + e)], 1);
}

#define SCAN_T 1024
#define SCAN_BLOCKS ((N_NODES + SCAN_T - 1) / SCAN_T)

__global__ __launch_bounds__(SCAN_T) void scanA_kernel() {
    __shared__ int sh[SCAN_T];
    int i = blockIdx.x * SCAN_T + threadIdx.x;
    int v = (i < N_NODES) ? g_deg[i] : 0;
    sh[threadIdx.x] = v;
    __syncthreads();
    int acc = v;
    for (int off = 1; off < SCAN_T; off <<= 1) {
        int t = (threadIdx.x >= off) ? sh[threadIdx.x - off] : 0;
        __syncthreads();
        acc += t;
        sh[threadIdx.x] = acc;
        __syncthreads();
    }
    if (i < N_NODES) g_row_ptr[i] = acc - v;
    if (threadIdx.x == SCAN_T - 1) g_blocksum[blockIdx.x] = acc;
}

__global__ void scanB_kernel() {
    __shared__ int sh[128];
    int t = threadIdx.x;
    int v = (t < SCAN_BLOCKS) ? g_blocksum[t] : 0;
    sh[t] = v;
    __syncthreads();
    int acc = v;
    for (int off = 1; off < 128; off <<= 1) {
        int tv = (t >= off) ? sh[t - off] : 0;
        __syncthreads();
        acc += tv;
        sh[t] = acc;
        __syncthreads();
    }
    if (t < SCAN_BLOCKS) g_blocksum[t] = acc - v;
}

__global__ __launch_bounds__(SCAN_T) void scanC_kernel() {
    int i = blockIdx.x * SCAN_T + threadIdx.x;
    if (i < N_NODES) {
        int r = g_row_ptr[i] + g_blocksum[blockIdx.x];
        g_row_ptr[i] = r;
        g_cursor[i] = r;
        g_deg_inv[i] = 1.0f / (float)max(g_deg[i], 1);
    }
    if (i == 0) g_row_ptr[N_NODES] = N_EDGES;
}

__global__ void fill_csr_kernel(const void* __restrict__ ei) {
    int e = blockIdx.x * blockDim.x + threadIdx.x;
    if (e < N_EDGES) {
        int src = load_edge(ei, e);
        int dst = load_edge(ei, (long)N_EDGES + e);
        int p = atomicAdd(&g_cursor[dst], 1);
        if (p < N_EDGES) g_col_idx[p] = src;
    }
}

// ---------------- W pre-split to bf16 fragment-major (once per launch) --------
__global__ void wsplit_kernel(const float* __restrict__ Wl,
                              const float* __restrict__ Wr) {
    int t = blockIdx.x * 256 + threadIdx.x;           // 6*2*4*1024
    if (t >= N_CONVS * 2 * 4 * 1024) return;
    int f     = t & 1023;
    int kc    = (t >> 10) & 3;
    int mat   = (t >> 12) & 1;
    int layer = t >> 13;
    int s  = f >> 9;
    int n  = (f >> 2) & 127;
    int qq = f & 3;
    const float* W = (mat ? Wr : Wl) + (long)layer * D * D;
    int kb = kc * 32 + s * 16 + 2 * qq;
    float w0 = W[(kb + 0) * D + n];
    float w1 = W[(kb + 1) * D + n];
    float w2 = W[(kb + 8) * D + n];
    float w3 = W[(kb + 9) * D + n];
    float h0 = bfhi(w0), h1 = bfhi(w1), h2 = bfhi(w2), h3 = bfhi(w3);
    uint2 hi, lo;
    hi.x = packbf(h0, h1);        hi.y = packbf(h2, h3);
    lo.x = packbf(w0 - h0, w1 - h1);
    lo.y = packbf(w2 - h2, w3 - h3);
    uint2* dst = g_Wbf + (long)(((layer * 2 + mat) * 4 + kc)) * 2048;
    dst[f] = hi;
    dst[1024 + f] = lo;
}

// ---------------- mean aggregation: one warp per node, 4-deep ILP ------------
__global__ __launch_bounds__(256) void agg_kernel(const float* __restrict__ x) {
    int warp = (blockIdx.x * blockDim.x + threadIdx.x) >> 5;
    int lane = threadIdx.x & 31;
    if (warp >= N_NODES) return;

    int e0 = g_row_ptr[warp];
    int e1 = g_row_ptr[warp + 1];
    const float4* x4 = (const float4*)x;

    float4 a0 = make_float4(0.f, 0.f, 0.f, 0.f);
    float4 a1 = a0, a2 = a0, a3 = a0;
    int e = e0;
    for (; e + 4 <= e1; e += 4) {
        int s0 = g_col_idx[e + 0];
        int s1 = g_col_idx[e + 1];
        int s2 = g_col_idx[e + 2];
        int s3 = g_col_idx[e + 3];
        float4 v0 = __ldg(&x4[(long)s0 * 32 + lane]);
        float4 v1 = __ldg(&x4[(long)s1 * 32 + lane]);
        float4 v2 = __ldg(&x4[(long)s2 * 32 + lane]);
        float4 v3 = __ldg(&x4[(long)s3 * 32 + lane]);
        a0.x += v0.x; a0.y += v0.y; a0.z += v0.z; a0.w += v0.w;
        a1.x += v1.x; a1.y += v1.y; a1.z += v1.z; a1.w += v1.w;
        a2.x += v2.x; a2.y += v2.y; a2.z += v2.z; a2.w += v2.w;
        a3.x += v3.x; a3.y += v3.y; a3.z += v3.z; a3.w += v3.w;
    }
    for (; e < e1; e++) {
        int s = g_col_idx[e];
        float4 v = __ldg(&x4[(long)s * 32 + lane]);
        a0.x += v.x; a0.y += v.y; a0.z += v.z; a0.w += v.w;
    }
    float di = g_deg_inv[warp];
    float4 acc;
    acc.x = (a0.x + a1.x + a2.x + a3.x) * di;
    acc.y = (a0.y + a1.y + a2.y + a3.y) * di;
    acc.z = (a0.z + a1.z + a2.z + a3.z) * di;
    acc.w = (a0.w + a1.w + a2.w + a3.w) * di;
    ((float4*)g_mean)[(long)warp * 32 + lane] = acc;
}

// ---------------- 3xBF16 tensor-core dual GEMM + bias + relu ------------------
// block 256 thr (8 warps), tile 128x128, warp tile 32(M)x64(N),
// mma.sync m16n8k16 bf16 -> fp32; hi/lo split for ~fp32 accuracy.
// Software pipeline: prefetch next iter's A/W into registers before the MMA
// stage so LDG latency hides behind tensor work.
#define APITCH 20

__device__ __forceinline__ void mma_bf16(float c[4],
                                         uint32_t a0, uint32_t a1,
                                         uint32_t a2, uint32_t a3,
                                         uint32_t b0, uint32_t b1) {
    asm volatile(
        "mma.sync.aligned.m16n8k16.row.col.f32.bf16.bf16.f32 "
        "{%0,%1,%2,%3}, {%4,%5,%6,%7}, {%8,%9}, {%0,%1,%2,%3};"
        : "+f"(c[0]), "+f"(c[1]), "+f"(c[2]), "+f"(c[3])
        : "r"(a0), "r"(a1), "r"(a2), "r"(a3), "r"(b0), "r"(b1));
}

__global__ __launch_bounds__(256, 2) void sage_gemm_bf16(
    const float* __restrict__ A0,    // mean [N,128]
    const float* __restrict__ A1,    // x    [N,128]
    const uint2* __restrict__ Wbf,   // this layer: 8*2048 uint2 (it = phase*4+kc)
    const float* __restrict__ bias,  // [128]
    float* __restrict__ Y)
{
    __shared__ __align__(16) uint32_t As[2][128][APITCH];  // [hi/lo][row][k-pair]
    __shared__ __align__(16) uint2    Ws[2][1024];         // [hi/lo][(s*128+n)*4+qq]

    const int tid  = threadIdx.x;
    const int wid  = tid >> 5;
    const int lane = tid & 31;
    const int rr   = lane >> 2;
    const int qq   = lane & 3;
    const int wm   = (wid & 3) * 32;
    const int wn   = (wid >> 2) * 64;
    const int row0 = blockIdx.x * 128;

    float c[2][8][4];
#pragma unroll
    for (int mt = 0; mt < 2; mt++)
#pragma unroll
        for (int nt = 0; nt < 8; nt++)
#pragma unroll
            for (int i = 0; i < 4; i++) c[mt][nt][i] = 0.f;

    const float4* A4s0 = (const float4*)A0;
    const float4* A4s1 = (const float4*)A1;

    float4 va[4];
    uint4  vw[4];

    // --- prologue: prefetch iter 0 (phase 0, kc 0) ---
    {
#pragma unroll
        for (int i = 0; i < 4; i++) {
            int idx = tid + i * 256;
            int r  = idx >> 3;
            int c4 = idx & 7;
            int rg = row0 + r;
            if (rg >= N_NODES) rg = N_NODES - 1;
            va[i] = A4s0[(long)rg * 32 + c4];
        }
        const uint4* src = (const uint4*)Wbf;
#pragma unroll
        for (int i = 0; i < 4; i++) vw[i] = src[tid + i * 256];
    }

    for (int it = 0; it < 8; ++it) {
        // --- store prefetched tile to smem (convert A to bf16 hi/lo) ---
#pragma unroll
        for (int i = 0; i < 4; i++) {
            int idx = tid + i * 256;
            int r  = idx >> 3;
            int c4 = idx & 7;
            float4 v = va[i];
            float hx = bfhi(v.x), hy = bfhi(v.y), hz = bfhi(v.z), hw = bfhi(v.w);
            As[0][r][c4 * 2 + 0] = packbf(hx, hy);
            As[0][r][c4 * 2 + 1] = packbf(hz, hw);
            As[1][r][c4 * 2 + 0] = packbf(v.x - hx, v.y - hy);
            As[1][r][c4 * 2 + 1] = packbf(v.z - hz, v.w - hw);
        }
        {
            uint4* dst = (uint4*)&Ws[0][0];
#pragma unroll
            for (int i = 0; i < 4; i++) dst[tid + i * 256] = vw[i];
        }
        __syncthreads();

        // --- prefetch next iter (LDG latency hides behind the MMA stage) ---
        if (it < 7) {
            int nit = it + 1;
            int kc = nit & 3;
            const float4* A4 = (nit >> 2) ? A4s1 : A4s0;
#pragma unroll
            for (int i = 0; i < 4; i++) {
                int idx = tid + i * 256;
                int r  = idx >> 3;
                int c4 = idx & 7;
                int rg = row0 + r;
                if (rg >= N_NODES) rg = N_NODES - 1;
                va[i] = A4[(long)rg * 32 + kc * 8 + c4];
            }
            const uint4* src = (const uint4*)(Wbf + (long)nit * 2048);
#pragma unroll
            for (int i = 0; i < 4; i++) vw[i] = src[tid + i * 256];
        }

        // --- compute ---
#pragma unroll
        for (int s = 0; s < 2; s++) {
            uint32_t ah[2][4], al[2][4];
#pragma unroll
            for (int mt = 0; mt < 2; mt++) {
                int r = wm + mt * 16 + rr;
                int p = s * 8 + qq;
                ah[mt][0] = As[0][r][p];
                ah[mt][1] = As[0][r + 8][p];
                ah[mt][2] = As[0][r][p + 4];
                ah[mt][3] = As[0][r + 8][p + 4];
                al[mt][0] = As[1][r][p];
                al[mt][1] = As[1][r + 8][p];
                al[mt][2] = As[1][r][p + 4];
                al[mt][3] = As[1][r + 8][p + 4];
            }
#pragma unroll
            for (int nt = 0; nt < 8; nt++) {
                int widx = (s * 128 + wn + nt * 8 + rr) * 4 + qq;
                uint2 bh = Ws[0][widx];
                uint2 bl = Ws[1][widx];
#pragma unroll
                for (int mt = 0; mt < 2; mt++) {
                    mma_bf16(c[mt][nt], ah[mt][0], ah[mt][1], ah[mt][2], ah[mt][3], bh.x, bh.y);
                    mma_bf16(c[mt][nt], ah[mt][0], ah[mt][1], ah[mt][2], ah[mt][3], bl.x, bl.y);
                    mma_bf16(c[mt][nt], al[mt][0], al[mt][1], al[mt][2], al[mt][3], bh.x, bh.y);
                }
            }
        }
        __syncthreads();
    }

    // epilogue: bias + relu (C frag rows rr/rr+8, cols 2qq,2qq+1)
#pragma unroll
    for (int mt = 0; mt < 2; mt++) {
#pragma unroll
        for (int half = 0; half < 2; half++) {
            int r = row0 + wm + mt * 16 + rr + half * 8;
            if (r < N_NODES) {
#pragma unroll
                for (int nt = 0; nt < 8; nt++) {
                    int col = wn + nt * 8 + 2 * qq;
                    float v0 = c[mt][nt][half * 2 + 0] + bias[col];
                    float v1 = c[mt][nt][half * 2 + 1] + bias[col + 1];
                    float2 o;
                    o.x = fmaxf(v0, 0.f);
                    o.y = fmaxf(v1, 0.f);
                    *(float2*)&Y[(long)r * 128 + col] = o;
                }
            }
        }
    }
}

// ---------------- final linear ------------------------------------------------
__global__ __launch_bounds__(256) void final_kernel(
    const float* __restrict__ x, const float* __restrict__ W_lin,
    const float* __restrict__ b_lin, float* __restrict__ out)
{
    int warp = (blockIdx.x * blockDim.x + threadIdx.x) >> 5;
    int lane = threadIdx.x & 31;
    if (warp >= N_NODES) return;

    const float4* x4 = (const float4*)x;
    float4 xv = x4[(long)warp * 32 + lane];
    float w0 = W_lin[lane * 4 + 0];
    float w1 = W_lin[lane * 4 + 1];
    float w2 = W_lin[lane * 4 + 2];
    float w3 = W_lin[lane * 4 + 3];
    float s = xv.x * w0 + xv.y * w1 + xv.z * w2 + xv.w * w3;
#pragma unroll
    for (int off = 16; off > 0; off >>= 1)
        s += __shfl_xor_sync(0xFFFFFFFFu, s, off);
    if (lane == 0) out[warp] = s + b_lin[0];
}

// ---------------- launch ------------------------------------------------------
extern "C" void kernel_launch(void* const* d_in, const int* in_sizes, int n_in,
                              void* d_out, int out_size)
{
    const float* x     = (const float*)d_in[0];
    const void*  ei    = d_in[1];
    const float* Wl    = (const float*)d_in[2];
    const float* Wr    = (const float*)d_in[3];
    const float* b     = (const float*)d_in[4];
    const float* W_lin = (const float*)d_in[5];
    const float* b_lin = (const float*)d_in[6];
    float*       out   = (float*)d_out;

    float *bufA, *bufB, *meanp;
    uint2* wbf;
    cudaGetSymbolAddress((void**)&bufA, g_bufA);
    cudaGetSymbolAddress((void**)&bufB, g_bufB);
    cudaGetSymbolAddress((void**)&meanp, g_mean);
    cudaGetSymbolAddress((void**)&wbf, g_Wbf);

    detect_kernel<<<1, 1>>>(ei);
    zero_deg_kernel<<<(N_NODES + 255) / 256, 256>>>();
    count_deg_kernel<<<(N_EDGES + 255) / 256, 256>>>(ei);
    scanA_kernel<<<SCAN_BLOCKS, SCAN_T>>>();
    scanB_kernel<<<1, 128>>>();
    scanC_kernel<<<SCAN_BLOCKS, SCAN_T>>>();
    fill_csr_kernel<<<(N_EDGES + 255) / 256, 256>>>(ei);
    wsplit_kernel<<<(N_CONVS * 2 * 4 * 1024 + 255) / 256, 256>>>(Wl, Wr);

    const int aggBlocks  = (N_NODES * 32 + 255) / 256;
    const int gemmBlocks = (N_NODES + 127) / 128;

    const float* cur = x;
    for (int i = 0; i < N_CONVS; i++) {
        float* nxt = (i & 1) ? bufB : bufA;
        agg_kernel<<<aggBlocks, 256>>>(cur);
        sage_gemm_bf16<<<gemmBlocks, 256>>>(
            meanp, cur, wbf + (long)i * 8 * 2048, b + (long)i * D, nxt);
        cur = nxt;
    }
    final_kernel<<<aggBlocks, 256>>>(cur, W_lin, b_lin, out);
}

// round 14
// speedup vs baseline: 1.5393x; 1.0071x over previous
#include <cuda_runtime.h>
#include <cuda_bf16.h>
#include <cstdint>

#define N_NODES 100000
#define N_EDGES 1600000
#define D 128
#define N_CONVS 6

// ---------------- scratch (static device memory; no allocs allowed) ----------
__device__ __align__(16) float g_bufA[N_NODES * D];
__device__ __align__(16) float g_bufB[N_NODES * D];
__device__ __align__(16) float g_mean[N_NODES * D];
// pre-split bf16 W, fragment-major: [layer][mat][kc(4)][hi:1024 | lo:1024] uint2
__device__ __align__(16) uint2 g_Wbf[N_CONVS * 2 * 4 * 2048];
__device__ float g_deg_inv[N_NODES];
__device__ int   g_deg[N_NODES];
__device__ int   g_row_ptr[N_NODES + 1];
__device__ int   g_cursor[N_NODES];
__device__ int   g_col_idx[N_EDGES];
__device__ int   g_blocksum[128];
__device__ int   g_is64;

// ---------------- helpers -----------------------------------------------------
__device__ __forceinline__ uint32_t packbf(float a, float b) {
    __nv_bfloat162 t = __floats2bfloat162_rn(a, b);   // .x = a (low half)
    return *(uint32_t*)&t;
}
__device__ __forceinline__ float bfhi(float w) {
    return __bfloat162float(__float2bfloat16_rn(w));
}

// ---------------- edge dtype detection ---------------------------------------
__global__ void detect_kernel(const void* __restrict__ ei) {
    const long long* p64 = (const long long*)ei;
    int ok = 1;
    for (int i = 0; i < 64; i++) {
        long long v = p64[i];
        if (v < 0 || v >= N_NODES) { ok = 0; break; }
    }
    g_is64 = ok;
}

__device__ __forceinline__ int load_edge(const void* ei, long idx) {
    long long v = g_is64 ? ((const long long*)ei)[idx]
                         : (long long)((const int*)ei)[idx];
    if ((unsigned long long)v >= (unsigned long long)N_NODES) v = 0;
    return (int)v;
}

// ---------------- CSR build --------------------------------------------------
__global__ void zero_deg_kernel() {
    int i = blockIdx.x * blockDim.x + threadIdx.x;
    if (i < N_NODES) g_deg[i] = 0;
}

__global__ void count_deg_kernel(const void* __restrict__ ei) {
    int e = blockIdx.x * blockDim.x + threadIdx.x;
    if (e < N_EDGES) atomicAdd(&g_deg[load_edge(ei, (long)N_EDGES + e)], 1);
}

#define SCAN_T 1024
#define SCAN_BLOCKS ((N_NODES + SCAN_T - 1) / SCAN_T)

__global__ __launch_bounds__(SCAN_T) void scanA_kernel() {
    __shared__ int sh[SCAN_T];
    int i = blockIdx.x * SCAN_T + threadIdx.x;
    int v = (i < N_NODES) ? g_deg[i] : 0;
    sh[threadIdx.x] = v;
    __syncthreads();
    int acc = v;
    for (int off = 1; off < SCAN_T; off <<= 1) {
        int t = (threadIdx.x >= off) ? sh[threadIdx.x - off] : 0;
        __syncthreads();
        acc += t;
        sh[threadIdx.x] = acc;
        __syncthreads();
    }
    if (i < N_NODES) g_row_ptr[i] = acc - v;
    if (threadIdx.x == SCAN_T - 1) g_blocksum[blockIdx.x] = acc;
}

__global__ void scanB_kernel() {
    __shared__ int sh[128];
    int t = threadIdx.x;
    int v = (t < SCAN_BLOCKS) ? g_blocksum[t] : 0;
    sh[t] = v;
    __syncthreads();
    int acc = v;
    for (int off = 1; off < 128; off <<= 1) {
        int tv = (t >= off) ? sh[t - off] : 0;
        __syncthreads();
        acc += tv;
        sh[t] = acc;
        __syncthreads();
    }
    if (t < SCAN_BLOCKS) g_blocksum[t] = acc - v;
}

__global__ __launch_bounds__(SCAN_T) void scanC_kernel() {
    int i = blockIdx.x * SCAN_T + threadIdx.x;
    if (i < N_NODES) {
        int r = g_row_ptr[i] + g_blocksum[blockIdx.x];
        g_row_ptr[i] = r;
        g_cursor[i] = r;
        g_deg_inv[i] = 1.0f / (float)max(g_deg[i], 1);
    }
    if (i == 0) g_row_ptr[N_NODES] = N_EDGES;
}

__global__ void fill_csr_kernel(const void* __restrict__ ei) {
    int e = blockIdx.x * blockDim.x + threadIdx.x;
    if (e < N_EDGES) {
        int src = load_edge(ei, e);
        int dst = load_edge(ei, (long)N_EDGES + e);
        int p = atomicAdd(&g_cursor[dst], 1);
        if (p < N_EDGES) g_col_idx[p] = src;
    }
}

// ---------------- W pre-split to bf16 fragment-major (once per launch) --------
__global__ void wsplit_kernel(const float* __restrict__ Wl,
                              const float* __restrict__ Wr) {
    int t = blockIdx.x * 256 + threadIdx.x;           // 6*2*4*1024
    if (t >= N_CONVS * 2 * 4 * 1024) return;
    int f     = t & 1023;
    int kc    = (t >> 10) & 3;
    int mat   = (t >> 12) & 1;
    int layer = t >> 13;
    int s  = f >> 9;
    int n  = (f >> 2) & 127;
    int qq = f & 3;
    const float* W = (mat ? Wr : Wl) + (long)layer * D * D;
    int kb = kc * 32 + s * 16 + 2 * qq;
    float w0 = W[(kb + 0) * D + n];
    float w1 = W[(kb + 1) * D + n];
    float w2 = W[(kb + 8) * D + n];
    float w3 = W[(kb + 9) * D + n];
    float h0 = bfhi(w0), h1 = bfhi(w1), h2 = bfhi(w2), h3 = bfhi(w3);
    uint2 hi, lo;
    hi.x = packbf(h0, h1);        hi.y = packbf(h2, h3);
    lo.x = packbf(w0 - h0, w1 - h1);
    lo.y = packbf(w2 - h2, w3 - h3);
    uint2* dst = g_Wbf + (long)(((layer * 2 + mat) * 4 + kc)) * 2048;
    dst[f] = hi;
    dst[1024 + f] = lo;
}

// ---------------- mean aggregation: one warp per node, 4-deep ILP ------------
__global__ __launch_bounds__(256) void agg_kernel(const float* __restrict__ x) {
    int warp = (blockIdx.x * blockDim.x + threadIdx.x) >> 5;
    int lane = threadIdx.x & 31;
    if (warp >= N_NODES) return;

    int e0 = g_row_ptr[warp];
    int e1 = g_row_ptr[warp + 1];
    const float4* x4 = (const float4*)x;

    float4 a0 = make_float4(0.f, 0.f, 0.f, 0.f);
    float4 a1 = a0, a2 = a0, a3 = a0;
    int e = e0;
    for (; e + 4 <= e1; e += 4) {
        int s0 = g_col_idx[e + 0];
        int s1 = g_col_idx[e + 1];
        int s2 = g_col_idx[e + 2];
        int s3 = g_col_idx[e + 3];
        float4 v0 = __ldg(&x4[(long)s0 * 32 + lane]);
        float4 v1 = __ldg(&x4[(long)s1 * 32 + lane]);
        float4 v2 = __ldg(&x4[(long)s2 * 32 + lane]);
        float4 v3 = __ldg(&x4[(long)s3 * 32 + lane]);
        a0.x += v0.x; a0.y += v0.y; a0.z += v0.z; a0.w += v0.w;
        a1.x += v1.x; a1.y += v1.y; a1.z += v1.z; a1.w += v1.w;
        a2.x += v2.x; a2.y += v2.y; a2.z += v2.z; a2.w += v2.w;
        a3.x += v3.x; a3.y += v3.y; a3.z += v3.z; a3.w += v3.w;
    }
    for (; e < e1; e++) {
        int s = g_col_idx[e];
        float4 v = __ldg(&x4[(long)s * 32 + lane]);
        a0.x += v.x; a0.y += v.y; a0.z += v.z; a0.w += v.w;
    }
    float di = g_deg_inv[warp];
    float4 acc;
    acc.x = (a0.x + a1.x + a2.x + a3.x) * di;
    acc.y = (a0.y + a1.y + a2.y + a3.y) * di;
    acc.z = (a0.z + a1.z + a2.z + a3.z) * di;
    acc.w = (a0.w + a1.w + a2.w + a3.w) * di;
    ((float4*)g_mean)[(long)warp * 32 + lane] = acc;
}

// ---------------- 3xBF16 tensor-core dual GEMM + bias + relu ------------------
// block 256 thr (8 warps), tile 128x128, warp tile 32(M)x64(N),
// mma.sync m16n8k16 bf16 -> fp32; hi/lo split for ~fp32 accuracy.
// Double-buffered smem + register prefetch: ONE sync per K-iteration.
#define APITCH 20
#define AS_BUF_STRIDE (2 * 128 * APITCH)      // 5120 u32 per buffer
#define WS_BASE_U32   (2 * AS_BUF_STRIDE)     // 10240
#define WS_BUF_STRIDE 2048                    // uint2 per buffer (hi 1024 | lo 1024)
#define SMEM_BYTES ((WS_BASE_U32 + 2 * WS_BUF_STRIDE * 2) * 4)   // 73728 B

__device__ __forceinline__ void mma_bf16(float c[4],
                                         uint32_t a0, uint32_t a1,
                                         uint32_t a2, uint32_t a3,
                                         uint32_t b0, uint32_t b1) {
    asm volatile(
        "mma.sync.aligned.m16n8k16.row.col.f32.bf16.bf16.f32 "
        "{%0,%1,%2,%3}, {%4,%5,%6,%7}, {%8,%9}, {%0,%1,%2,%3};"
        : "+f"(c[0]), "+f"(c[1]), "+f"(c[2]), "+f"(c[3])
        : "r"(a0), "r"(a1), "r"(a2), "r"(a3), "r"(b0), "r"(b1));
}

__global__ __launch_bounds__(256, 2) void sage_gemm_bf16(
    const float* __restrict__ A0,    // mean [N,128]
    const float* __restrict__ A1,    // x    [N,128]
    const uint2* __restrict__ Wbf,   // this layer: 8*2048 uint2 (it = phase*4+kc)
    const float* __restrict__ bias,  // [128]
    float* __restrict__ Y)
{
    extern __shared__ __align__(16) uint32_t dsm[];
    uint32_t* AsB = dsm;                                  // 2 buffers
    uint2*    WsB = (uint2*)(dsm + WS_BASE_U32);          // 2 buffers

    const int tid  = threadIdx.x;
    const int wid  = tid >> 5;
    const int lane = tid & 31;
    const int rr   = lane >> 2;
    const int qq   = lane & 3;
    const int wm   = (wid & 3) * 32;
    const int wn   = (wid >> 2) * 64;
    const int row0 = blockIdx.x * 128;

    float c[2][8][4];
#pragma unroll
    for (int mt = 0; mt < 2; mt++)
#pragma unroll
        for (int nt = 0; nt < 8; nt++)
#pragma unroll
            for (int i = 0; i < 4; i++) c[mt][nt][i] = 0.f;

    const float4* A4s0 = (const float4*)A0;
    const float4* A4s1 = (const float4*)A1;

    float4 va[4];
    uint4  vw[4];

    // --- prologue: prefetch iter 0 (phase 0, kc 0) ---
    {
#pragma unroll
        for (int i = 0; i < 4; i++) {
            int idx = tid + i * 256;
            int r  = idx >> 3;
            int c4 = idx & 7;
            int rg = row0 + r;
            if (rg >= N_NODES) rg = N_NODES - 1;
            va[i] = A4s0[(long)rg * 32 + c4];
        }
        const uint4* src = (const uint4*)Wbf;
#pragma unroll
        for (int i = 0; i < 4; i++) vw[i] = src[tid + i * 256];
    }

    for (int it = 0; it < 8; ++it) {
        const int bi = it & 1;
        uint32_t* As = AsB + bi * AS_BUF_STRIDE;          // [hi/lo][128][APITCH]
        uint2*    Ws = WsB + bi * WS_BUF_STRIDE;          // [hi/lo][1024]

        // --- store prefetched tile to this iteration's buffer ---
#pragma unroll
        for (int i = 0; i < 4; i++) {
            int idx = tid + i * 256;
            int r  = idx >> 3;
            int c4 = idx & 7;
            float4 v = va[i];
            float hx = bfhi(v.x), hy = bfhi(v.y), hz = bfhi(v.z), hw = bfhi(v.w);
            As[r * APITCH + c4 * 2 + 0] = packbf(hx, hy);
            As[r * APITCH + c4 * 2 + 1] = packbf(hz, hw);
            As[128 * APITCH + r * APITCH + c4 * 2 + 0] = packbf(v.x - hx, v.y - hy);
            As[128 * APITCH + r * APITCH + c4 * 2 + 1] = packbf(v.z - hz, v.w - hw);
        }
        {
            uint4* dst = (uint4*)Ws;
#pragma unroll
            for (int i = 0; i < 4; i++) dst[tid + i * 256] = vw[i];
        }
        __syncthreads();    // the ONLY sync per iteration

        // --- prefetch next iter into regs (no smem hazard: other buffer) ---
        if (it < 7) {
            int nit = it + 1;
            int kc = nit & 3;
            const float4* A4 = (nit >> 2) ? A4s1 : A4s0;
#pragma unroll
            for (int i = 0; i < 4; i++) {
                int idx = tid + i * 256;
                int r  = idx >> 3;
                int c4 = idx & 7;
                int rg = row0 + r;
                if (rg >= N_NODES) rg = N_NODES - 1;
                va[i] = A4[(long)rg * 32 + kc * 8 + c4];
            }
            const uint4* src = (const uint4*)(Wbf + (long)nit * 2048);
#pragma unroll
            for (int i = 0; i < 4; i++) vw[i] = src[tid + i * 256];
        }

        // --- compute from buffer bi ---
#pragma unroll
        for (int s = 0; s < 2; s++) {
            uint32_t ah[2][4], al[2][4];
#pragma unroll
            for (int mt = 0; mt < 2; mt++) {
                int r = wm + mt * 16 + rr;
                int p = s * 8 + qq;
                ah[mt][0] = As[r * APITCH + p];
                ah[mt][1] = As[(r + 8) * APITCH + p];
                ah[mt][2] = As[r * APITCH + p + 4];
                ah[mt][3] = As[(r + 8) * APITCH + p + 4];
                al[mt][0] = As[128 * APITCH + r * APITCH + p];
                al[mt][1] = As[128 * APITCH + (r + 8) * APITCH + p];
                al[mt][2] = As[128 * APITCH + r * APITCH + p + 4];
                al[mt][3] = As[128 * APITCH + (r + 8) * APITCH + p + 4];
            }
#pragma unroll
            for (int nt = 0; nt < 8; nt++) {
                int widx = (s * 128 + wn + nt * 8 + rr) * 4 + qq;
                uint2 bh = Ws[widx];
                uint2 bl = Ws[1024 + widx];
#pragma unroll
                for (int mt = 0; mt < 2; mt++) {
                    mma_bf16(c[mt][nt], ah[mt][0], ah[mt][1], ah[mt][2], ah[mt][3], bh.x, bh.y);
                    mma_bf16(c[mt][nt], ah[mt][0], ah[mt][1], ah[mt][2], ah[mt][3], bl.x, bl.y);
                    mma_bf16(c[mt][nt], al[mt][0], al[mt][1], al[mt][2], al[mt][3], bh.x, bh.y);
                }
            }
        }
        // no trailing sync: next iteration writes the OTHER buffer, and its
        // sync (after store) orders it against all warps' compute of it-1.
    }

    // epilogue: bias + relu (C frag rows rr/rr+8, cols 2qq,2qq+1)
#pragma unroll
    for (int mt = 0; mt < 2; mt++) {
#pragma unroll
        for (int half = 0; half < 2; half++) {
            int r = row0 + wm + mt * 16 + rr + half * 8;
            if (r < N_NODES) {
#pragma unroll
                for (int nt = 0; nt < 8; nt++) {
                    int col = wn + nt * 8 + 2 * qq;
                    float v0 = c[mt][nt][half * 2 + 0] + bias[col];
                    float v1 = c[mt][nt][half * 2 + 1] + bias[col + 1];
                    float2 o;
                    o.x = fmaxf(v0, 0.f);
                    o.y = fmaxf(v1, 0.f);
                    *(float2*)&Y[(long)r * 128 + col] = o;
                }
            }
        }
    }
}

// ---------------- final linear ------------------------------------------------
__global__ __launch_bounds__(256) void final_kernel(
    const float* __restrict__ x, const float* __restrict__ W_lin,
    const float* __restrict__ b_lin, float* __restrict__ out)
{
    int warp = (blockIdx.x * blockDim.x + threadIdx.x) >> 5;
    int lane = threadIdx.x & 31;
    if (warp >= N_NODES) return;

    const float4* x4 = (const float4*)x;
    float4 xv = x4[(long)warp * 32 + lane];
    float w0 = W_lin[lane * 4 + 0];
    float w1 = W_lin[lane * 4 + 1];
    float w2 = W_lin[lane * 4 + 2];
    float w3 = W_lin[lane * 4 + 3];
    float s = xv.x * w0 + xv.y * w1 + xv.z * w2 + xv.w * w3;
#pragma unroll
    for (int off = 16; off > 0; off >>= 1)
        s += __shfl_xor_sync(0xFFFFFFFFu, s, off);
    if (lane == 0) out[warp] = s + b_lin[0];
}

// ---------------- launch ------------------------------------------------------
extern "C" void kernel_launch(void* const* d_in, const int* in_sizes, int n_in,
                              void* d_out, int out_size)
{
    const float* x     = (const float*)d_in[0];
    const void*  ei    = d_in[1];
    const float* Wl    = (const float*)d_in[2];
    const float* Wr    = (const float*)d_in[3];
    const float* b     = (const float*)d_in[4];
    const float* W_lin = (const float*)d_in[5];
    const float* b_lin = (const float*)d_in[6];
    float*       out   = (float*)d_out;

    float *bufA, *bufB, *meanp;
    uint2* wbf;
    cudaGetSymbolAddress((void**)&bufA, g_bufA);
    cudaGetSymbolAddress((void**)&bufB, g_bufB);
    cudaGetSymbolAddress((void**)&meanp, g_mean);
    cudaGetSymbolAddress((void**)&wbf, g_Wbf);

    cudaFuncSetAttribute(sage_gemm_bf16,
                         cudaFuncAttributeMaxDynamicSharedMemorySize, SMEM_BYTES);

    detect_kernel<<<1, 1>>>(ei);
    zero_deg_kernel<<<(N_NODES + 255) / 256, 256>>>();
    count_deg_kernel<<<(N_EDGES + 255) / 256, 256>>>(ei);
    scanA_kernel<<<SCAN_BLOCKS, SCAN_T>>>();
    scanB_kernel<<<1, 128>>>();
    scanC_kernel<<<SCAN_BLOCKS, SCAN_T>>>();
    fill_csr_kernel<<<(N_EDGES + 255) / 256, 256>>>(ei);
    wsplit_kernel<<<(N_CONVS * 2 * 4 * 1024 + 255) / 256, 256>>>(Wl, Wr);

    const int aggBlocks  = (N_NODES * 32 + 255) / 256;
    const int gemmBlocks = (N_NODES + 127) / 128;

    const float* cur = x;
    for (int i = 0; i < N_CONVS; i++) {
        float* nxt = (i & 1) ? bufB : bufA;
        agg_kernel<<<aggBlocks, 256>>>(cur);
        sage_gemm_bf16<<<gemmBlocks, 256, SMEM_BYTES>>>(
            meanp, cur, wbf + (long)i * 8 * 2048, b + (long)i * D, nxt);
        cur = nxt;
    }
    final_kernel<<<aggBlocks, 256>>>(cur, W_lin, b_lin, out);
}